// round 17
// baseline (speedup 1.0000x reference)
#include <cuda_runtime.h>
#include <cuda_bf16.h>
#include <math.h>

// Problem constants
#define BB 4
#define CC 64
#define OO 64
#define HH 128
#define WW 128
#define HW (HH*WW)
#define K2 9

// Scratch (device globals; no allocation allowed)
__device__ float g_wdef_t[K2 * CC * OO];      // [k][c][o]
__device__ int4   g_idx[BB * K2 * HW];        // 4 clamped flat indices per (b,k,pix)
__device__ float4 g_wgt[BB * K2 * HW];        // 4 bilinear weights (mask/validity folded)

// ---------------------------------------------------------------------------
// Kernel A (FIRST LAUNCH -> ncu capture target): 3x3 offset conv (27 ch)
// + bilinear record construction. Vectorized weight LDS (float4).
// grid: (H, B), block: 128 threads.
// ---------------------------------------------------------------------------
__global__ __launch_bounds__(WW) void koffset(const float* __restrict__ feat,
                                              const float* __restrict__ w_off,
                                              const float* __restrict__ b_off) {
    const int w = threadIdx.x;
    const int h = blockIdx.x;
    const int b = blockIdx.y;

    __shared__ float fs[3][132];        // 3 feat rows, zero-padded borders
    __shared__ float wsm[27 * 12];      // per-channel weight slice [oc][k], pad 12
                                        // row stride 48B -> 16B-aligned rows

    float acc[27];
#pragma unroll
    for (int i = 0; i < 27; i++) acc[i] = 0.f;

    const float* fb = feat + (size_t)b * CC * HW;

    for (int c = 0; c < CC; c++) {
        // stage this channel's weights straight from w_off[oc][c][k]
        for (int i = threadIdx.x; i < 27 * K2; i += WW) {
            int oc = i / K2, k = i % K2;
            wsm[oc * 12 + k] = w_off[oc * (CC * K2) + c * K2 + k];
        }
        // stage 3 feat rows (zero-padded top/bottom)
#pragma unroll
        for (int r = 0; r < 3; r++) {
            int y = h + r - 1;
            float v = (y >= 0 && y < HH) ? fb[c * HW + y * WW + w] : 0.f;
            fs[r][w + 1] = v;
        }
        if (w == 0)    { fs[0][0]   = 0.f; fs[1][0]   = 0.f; fs[2][0]   = 0.f; }
        if (w == WW-1) { fs[0][129] = 0.f; fs[1][129] = 0.f; fs[2][129] = 0.f; }
        __syncthreads();

        float v[9];
#pragma unroll
        for (int ky = 0; ky < 3; ky++)
#pragma unroll
            for (int kx = 0; kx < 3; kx++)
                v[ky * 3 + kx] = fs[ky][w + kx];

#pragma unroll
        for (int oc = 0; oc < 27; oc++) {
            const float4 wa = *reinterpret_cast<const float4*>(&wsm[oc * 12]);
            const float4 wb = *reinterpret_cast<const float4*>(&wsm[oc * 12 + 4]);
            const float  w8 = wsm[oc * 12 + 8];
            float s = acc[oc];
            s = fmaf(v[0], wa.x, s);
            s = fmaf(v[1], wa.y, s);
            s = fmaf(v[2], wa.z, s);
            s = fmaf(v[3], wa.w, s);
            s = fmaf(v[4], wb.x, s);
            s = fmaf(v[5], wb.y, s);
            s = fmaf(v[6], wb.z, s);
            s = fmaf(v[7], wb.w, s);
            s = fmaf(v[8], w8,   s);
            acc[oc] = s;
        }
        __syncthreads();
    }

    // epilogue: bias, sigmoid mask, bilinear records
    const int pix = h * WW + w;
#pragma unroll
    for (int k = 0; k < K2; k++) {
        float ox = acc[k]      + b_off[k];
        float oy = acc[9 + k]  + b_off[9 + k];
        float mm = acc[18 + k] + b_off[18 + k];
        float mask = 1.f / (1.f + expf(-mm));

        float ys = (float)h + (float)(k / 3 - 1) + oy;
        float xs = (float)w + (float)(k % 3 - 1) + ox;
        float y0f = floorf(ys), x0f = floorf(xs);
        float wy1 = ys - y0f, wx1 = xs - x0f;
        float wy0 = 1.f - wy1, wx0 = 1.f - wx1;
        int y0 = (int)y0f, x0 = (int)x0f;
        int y1 = y0 + 1,  x1 = x0 + 1;

        float vy0 = (y0 >= 0 && y0 < HH) ? 1.f : 0.f;
        float vy1 = (y1 >= 0 && y1 < HH) ? 1.f : 0.f;
        float vx0 = (x0 >= 0 && x0 < WW) ? 1.f : 0.f;
        float vx1 = (x1 >= 0 && x1 < WW) ? 1.f : 0.f;

        int cy0 = min(max(y0, 0), HH - 1);
        int cy1 = min(max(y1, 0), HH - 1);
        int cx0 = min(max(x0, 0), WW - 1);
        int cx1 = min(max(x1, 0), WW - 1);

        int4 ii;
        ii.x = cy0 * WW + cx0;
        ii.y = cy0 * WW + cx1;
        ii.z = cy1 * WW + cx0;
        ii.w = cy1 * WW + cx1;
        float4 ww;
        ww.x = wy0 * wx0 * mask * vy0 * vx0;
        ww.y = wy0 * wx1 * mask * vy0 * vx1;
        ww.z = wy1 * wx0 * mask * vy1 * vx0;
        ww.w = wy1 * wx1 * mask * vy1 * vx1;

        int rid = (b * K2 + k) * HW + pix;
        g_idx[rid] = ii;
        g_wgt[rid] = ww;
    }
}

// ---------------------------------------------------------------------------
// Kernel W: transpose w_def -> [k][c][o]
// ---------------------------------------------------------------------------
__global__ void ktransw(const float* __restrict__ w_def) {
    int i = blockIdx.x * 256 + threadIdx.x;
    if (i < K2 * CC * OO) {
        int k = i / (CC * OO);
        int r = i % (CC * OO);
        int c = r / OO;
        int o = r % OO;
        g_wdef_t[i] = w_def[o * (CC * K2) + c * K2 + k];
    }
}

// ---------------------------------------------------------------------------
// Kernel B: fused deformable sampling + GEMM + bias + relu
// Occupancy experiment: grid (H, B, 2); each block computes 32 of the 64
// outputs (acc[32] -> ~88 regs -> ~23 warps/SM instead of reg-capped 16).
// ---------------------------------------------------------------------------
__global__ __launch_bounds__(WW) void kdeform(const float* __restrict__ x,
                                              const float* __restrict__ b_def,
                                              float* __restrict__ out) {
    const int w = threadIdx.x;
    const int h = blockIdx.x;
    const int b = blockIdx.y;
    const int o0 = blockIdx.z * 32;          // output-half base
    const int pix = h * WW + w;

    __shared__ float wk[CC * 32];   // w_def slice for current tap: [c][o-half], 8 KB

    float acc[32];
#pragma unroll
    for (int o = 0; o < 32; o++) acc[o] = 0.f;

    const float* xb = x + (size_t)b * CC * HW;

    for (int k = 0; k < K2; k++) {
        __syncthreads();
        for (int i = threadIdx.x; i < CC * 32; i += WW) {
            int c = i >> 5, o = i & 31;
            wk[i] = g_wdef_t[k * (CC * OO) + c * OO + o0 + o];
        }
        __syncthreads();

        const int rid = (b * K2 + k) * HW + pix;
        const int4   ii = g_idx[rid];
        const float4 ww = g_wgt[rid];

#pragma unroll 4
        for (int c = 0; c < CC; c++) {
            const float* xc = xb + c * HW;
            float col = ww.x * __ldg(xc + ii.x)
                      + ww.y * __ldg(xc + ii.y)
                      + ww.z * __ldg(xc + ii.z)
                      + ww.w * __ldg(xc + ii.w);
            const float* wrow = &wk[c * 32];
#pragma unroll
            for (int o = 0; o < 32; o++) acc[o] += col * wrow[o];
        }
    }

#pragma unroll
    for (int o = 0; o < 32; o++) {
        float r = acc[o] + b_def[o0 + o];
        out[((size_t)(b * OO + o0 + o)) * HW + pix] = fmaxf(r, 0.f);
    }
}

// ---------------------------------------------------------------------------
extern "C" void kernel_launch(void* const* d_in, const int* in_sizes, int n_in,
                              void* d_out, int out_size) {
    const float* x     = (const float*)d_in[0];
    const float* feat  = (const float*)d_in[1];
    const float* w_off = (const float*)d_in[2];
    const float* b_off = (const float*)d_in[3];
    const float* w_def = (const float*)d_in[4];
    const float* b_def = (const float*)d_in[5];
    float* out = (float*)d_out;

    dim3 gridA(HH, BB);
    koffset<<<gridA, WW>>>(feat, w_off, b_off);           // launch 0 -> profiled

    ktransw<<<(K2 * CC * OO + 255) / 256, 256>>>(w_def);  // launch 1

    dim3 gridB(HH, BB, 2);
    kdeform<<<gridB, WW>>>(x, b_def, out);                // launch 2
}